// round 1
// baseline (speedup 1.0000x reference)
#include <cuda_runtime.h>
#include <cuda_bf16.h>
#include <math.h>

// Problem constants
#define BATCH 2
#define SEQ   2048
#define CDIM  1024
#define NHEAD 16
#define HDIM  64
#define ROWS  (BATCH * SEQ)          // 4096
#define HID   (4 * CDIM)             // 4096

// ---------------- scratch (static device globals; no allocation) ----------------
__device__ float g_qkv[(size_t)ROWS * 3 * CDIM];   // 4096 x 3072
__device__ float g_y  [(size_t)ROWS * CDIM];       // attention output
__device__ float g_h  [(size_t)ROWS * HID];        // FF hidden (reused)
__device__ float g_t  [(size_t)ROWS * CDIM];       // FF output (reused)
__device__ float g_x1 [(size_t)ROWS * CDIM];       // after first residual

// ---------------- GEMM: C = act(A @ B + bias) ----------------
// A: MxK row-major, B: KxN row-major, C: MxN row-major.
// 128x128 block tile, BK=8, 256 threads, 8x8 per thread, double-buffered smem.
template<bool GELU>
__global__ __launch_bounds__(256) void gemm_bias_kernel(
    const float* __restrict__ A, const float* __restrict__ B,
    const float* __restrict__ bias, float* __restrict__ C,
    int M, int N, int K)
{
    __shared__ float As[2][8][132];
    __shared__ float Bs[2][8][128];

    const int tid = threadIdx.x;
    const int bm = blockIdx.y * 128;
    const int bn = blockIdx.x * 128;

    // A tile load mapping: row = tid/2 (0..127), k-offset = (tid&1)*4
    const int a_row = tid >> 1;
    const int a_k   = (tid & 1) * 4;
    // B tile load mapping: k-row = tid/32 (0..7), col = (tid&31)*4
    const int b_k   = tid >> 5;
    const int b_col = (tid & 31) * 4;

    const float* Aptr = A + (size_t)(bm + a_row) * K + a_k;
    const float* Bptr = B + (size_t)b_k * N + bn + b_col;

    // compute mapping
    const int ty = tid >> 4;      // 0..15
    const int tx = tid & 15;      // 0..15
    const int row0 = ty * 4;      // rows row0..+3 and row0+64..+67
    const int col0 = tx * 4;      // cols col0..+3 and col0+64..+67

    float acc[8][8];
    #pragma unroll
    for (int i = 0; i < 8; ++i)
        #pragma unroll
        for (int j = 0; j < 8; ++j) acc[i][j] = 0.f;

    // prologue: load tile 0
    {
        float4 av = *(const float4*)(Aptr);
        float4 bv = *(const float4*)(Bptr);
        As[0][a_k + 0][a_row] = av.x;
        As[0][a_k + 1][a_row] = av.y;
        As[0][a_k + 2][a_row] = av.z;
        As[0][a_k + 3][a_row] = av.w;
        *(float4*)&Bs[0][b_k][b_col] = bv;
    }
    __syncthreads();

    const int nk = K >> 3;
    for (int t = 0; t < nk; ++t) {
        const int cur = t & 1;
        float4 av, bv;
        const bool has = (t + 1 < nk);
        if (has) {
            av = *(const float4*)(Aptr + (t + 1) * 8);
            bv = *(const float4*)(Bptr + (size_t)(t + 1) * 8 * N);
        }
        #pragma unroll
        for (int k = 0; k < 8; ++k) {
            float a[8], b[8];
            *(float4*)&a[0] = *(const float4*)&As[cur][k][row0];
            *(float4*)&a[4] = *(const float4*)&As[cur][k][row0 + 64];
            *(float4*)&b[0] = *(const float4*)&Bs[cur][k][col0];
            *(float4*)&b[4] = *(const float4*)&Bs[cur][k][col0 + 64];
            #pragma unroll
            for (int i = 0; i < 8; ++i)
                #pragma unroll
                for (int j = 0; j < 8; ++j)
                    acc[i][j] = fmaf(a[i], b[j], acc[i][j]);
        }
        if (has) {
            const int nx = cur ^ 1;
            As[nx][a_k + 0][a_row] = av.x;
            As[nx][a_k + 1][a_row] = av.y;
            As[nx][a_k + 2][a_row] = av.z;
            As[nx][a_k + 3][a_row] = av.w;
            *(float4*)&Bs[nx][b_k][b_col] = bv;
        }
        __syncthreads();
    }

    // epilogue
    #pragma unroll
    for (int ii = 0; ii < 2; ++ii) {
        #pragma unroll
        for (int i = 0; i < 4; ++i) {
            const int r = bm + ii * 64 + row0 + i;
            float* cp = C + (size_t)r * N + bn;
            #pragma unroll
            for (int jj = 0; jj < 2; ++jj) {
                const int cbase = jj * 64 + col0;
                float4 bv4 = *(const float4*)(bias + bn + cbase);
                float v0 = acc[ii * 4 + i][jj * 4 + 0] + bv4.x;
                float v1 = acc[ii * 4 + i][jj * 4 + 1] + bv4.y;
                float v2 = acc[ii * 4 + i][jj * 4 + 2] + bv4.z;
                float v3 = acc[ii * 4 + i][jj * 4 + 3] + bv4.w;
                if (GELU) {
                    v0 *= normcdff(v0);
                    v1 *= normcdff(v1);
                    v2 *= normcdff(v2);
                    v3 *= normcdff(v3);
                }
                float4 res = make_float4(v0, v1, v2, v3);
                *(float4*)(cp + cbase) = res;
            }
        }
    }
}

// ---------------- Flash attention (causal) ----------------
// qkv layout: [B, T, 3C] with split order K | Q | V (K at 0, Q at C, V at 2C).
// Head h occupies channels h*64 .. h*64+63.
// Block: 256 threads, 64 queries per block; 4 threads per query, each owning
// a 16-dim slice of HD=64. K/V tiles of 64 keys staged in smem.
__global__ __launch_bounds__(256) void attn_kernel(
    const float* __restrict__ qkv, float* __restrict__ y)
{
    const int b = blockIdx.z;
    const int h = blockIdx.y;
    const int q0 = blockIdx.x * 64;
    const int tid = threadIdx.x;
    const int q = tid >> 2;              // query row in tile (0..63)
    const int dseg = (tid & 3) * 16;     // dim slice start

    __shared__ float Ks[64][64];
    __shared__ float Vs[64][64];

    // Q row slice into registers
    float Qr[16];
    {
        const float* qptr = qkv + ((size_t)b * SEQ + (q0 + q)) * (3 * CDIM)
                            + CDIM + h * HDIM + dseg;
        #pragma unroll
        for (int i = 0; i < 16; i += 4)
            *(float4*)&Qr[i] = *(const float4*)(qptr + i);
    }

    float m = -INFINITY, l = 0.f;
    float o[16];
    #pragma unroll
    for (int j = 0; j < 16; ++j) o[j] = 0.f;

    const int ld_row = tid >> 2;
    const int ld_col = (tid & 3) * 16;

    const int ntiles = q0 / 64 + 1;  // causal: only tiles with k0 <= q0
    for (int kt = 0; kt < ntiles; ++kt) {
        const int k0 = kt * 64;
        const float* kbase = qkv + ((size_t)b * SEQ + (k0 + ld_row)) * (3 * CDIM)
                             + h * HDIM + ld_col;            // K at offset 0
        const float* vbase = kbase + 2 * CDIM;               // V at offset 2C
        __syncthreads();
        #pragma unroll
        for (int i = 0; i < 16; i += 4) {
            *(float4*)&Ks[ld_row][ld_col + i] = *(const float4*)(kbase + i);
            *(float4*)&Vs[ld_row][ld_col + i] = *(const float4*)(vbase + i);
        }
        __syncthreads();

        // partial scores over this thread's 16 dims, all 64 keys
        float s[64];
        #pragma unroll
        for (int k = 0; k < 64; ++k) {
            float a = 0.f;
            #pragma unroll
            for (int j = 0; j < 16; j += 4) {
                float4 kv = *(const float4*)&Ks[k][dseg + j];
                a = fmaf(Qr[j + 0], kv.x, a);
                a = fmaf(Qr[j + 1], kv.y, a);
                a = fmaf(Qr[j + 2], kv.z, a);
                a = fmaf(Qr[j + 3], kv.w, a);
            }
            s[k] = a;
        }
        // combine the 4 dim-slices (lanes l, l^1, l^2 within 4-group)
        #pragma unroll
        for (int k = 0; k < 64; ++k) {
            float v = s[k];
            v += __shfl_xor_sync(0xffffffffu, v, 1);
            v += __shfl_xor_sync(0xffffffffu, v, 2);
            s[k] = v * 0.125f;   // 1/sqrt(64)
        }
        // causal mask (only the diagonal tile needs it)
        if (k0 + 63 > q0 + q) {
            #pragma unroll
            for (int k = 0; k < 64; ++k)
                if (k0 + k > q0 + q) s[k] = -INFINITY;
        }
        // online softmax
        float mt = -INFINITY;
        #pragma unroll
        for (int k = 0; k < 64; ++k) mt = fmaxf(mt, s[k]);
        const float mn = fmaxf(m, mt);
        const float scale = __expf(m - mn);   // m=-inf first iter -> 0
        float ls = 0.f;
        #pragma unroll
        for (int k = 0; k < 64; ++k) {
            const float p = __expf(s[k] - mn);
            s[k] = p;
            ls += p;
        }
        l = l * scale + ls;
        m = mn;
        #pragma unroll
        for (int j = 0; j < 16; ++j) o[j] *= scale;
        // o += P @ V (this thread's 16 dims)
        #pragma unroll
        for (int k = 0; k < 64; ++k) {
            const float p = s[k];
            #pragma unroll
            for (int j = 0; j < 16; j += 4) {
                float4 vv = *(const float4*)&Vs[k][dseg + j];
                o[j + 0] = fmaf(p, vv.x, o[j + 0]);
                o[j + 1] = fmaf(p, vv.y, o[j + 1]);
                o[j + 2] = fmaf(p, vv.z, o[j + 2]);
                o[j + 3] = fmaf(p, vv.w, o[j + 3]);
            }
        }
    }

    const float rl = 1.f / l;
    float* yp = y + ((size_t)b * SEQ + (q0 + q)) * CDIM + h * HDIM + dseg;
    #pragma unroll
    for (int j = 0; j < 16; j += 4) {
        float4 ov = make_float4(o[j] * rl, o[j + 1] * rl, o[j + 2] * rl, o[j + 3] * rl);
        *(float4*)(yp + j) = ov;
    }
}

// ---------------- residual + LayerNorm: out = xres + LN(v)*g + be ----------------
__device__ __forceinline__ float block_sum256(float v, float* red) {
    const int lane = threadIdx.x & 31;
    const int w = threadIdx.x >> 5;
    #pragma unroll
    for (int off = 16; off; off >>= 1) v += __shfl_xor_sync(0xffffffffu, v, off);
    if (lane == 0) red[w] = v;
    __syncthreads();
    float t = (threadIdx.x < 8) ? red[threadIdx.x] : 0.f;
    if (w == 0) {
        t += __shfl_xor_sync(0xffffffffu, t, 4);
        t += __shfl_xor_sync(0xffffffffu, t, 2);
        t += __shfl_xor_sync(0xffffffffu, t, 1);
        if (lane == 0) red[0] = t;
    }
    __syncthreads();
    const float r = red[0];
    __syncthreads();
    return r;
}

__global__ __launch_bounds__(256) void add_ln_kernel(
    const float* __restrict__ xres, const float* __restrict__ v,
    const float* __restrict__ g, const float* __restrict__ be,
    float* __restrict__ out)
{
    __shared__ float red[8];
    const size_t row = blockIdx.x;
    const int c0 = threadIdx.x * 4;
    const float* vr = v + row * CDIM;

    float vals[4];
    *(float4*)vals = *(const float4*)(vr + c0);
    float s = vals[0] + vals[1] + vals[2] + vals[3];
    const float mean = block_sum256(s, red) * (1.f / CDIM);

    float d2 = 0.f;
    #pragma unroll
    for (int i = 0; i < 4; ++i) {
        const float d = vals[i] - mean;
        d2 = fmaf(d, d, d2);
    }
    const float var = block_sum256(d2, red) * (1.f / CDIM);
    const float rstd = rsqrtf(var + 1e-5f);

    float4 xr = *(const float4*)(xres + row * CDIM + c0);
    float4 gg = *(const float4*)(g + c0);
    float4 bb = *(const float4*)(be + c0);
    float4 res;
    res.x = xr.x + (vals[0] - mean) * rstd * gg.x + bb.x;
    res.y = xr.y + (vals[1] - mean) * rstd * gg.y + bb.y;
    res.z = xr.z + (vals[2] - mean) * rstd * gg.z + bb.z;
    res.w = xr.w + (vals[3] - mean) * rstd * gg.w + bb.w;
    *(float4*)(out + row * CDIM + c0) = res;
}

// ---------------- launch ----------------
extern "C" void kernel_launch(void* const* d_in, const int* in_sizes, int n_in,
                              void* d_out, int out_size)
{
    const float* x      = (const float*)d_in[0];
    const float* w_attn = (const float*)d_in[1];
    const float* b_attn = (const float*)d_in[2];
    const float* wa1    = (const float*)d_in[3];
    const float* ba1    = (const float*)d_in[4];
    const float* wa2    = (const float*)d_in[5];
    const float* ba2    = (const float*)d_in[6];
    const float* g1     = (const float*)d_in[7];
    const float* be1    = (const float*)d_in[8];
    const float* wf1    = (const float*)d_in[9];
    const float* bf1    = (const float*)d_in[10];
    const float* wf2    = (const float*)d_in[11];
    const float* bf2    = (const float*)d_in[12];
    const float* g2     = (const float*)d_in[13];
    const float* be2    = (const float*)d_in[14];
    float* out = (float*)d_out;

    float *qkv, *y, *hbuf, *tbuf, *x1;
    cudaGetSymbolAddress((void**)&qkv,  g_qkv);
    cudaGetSymbolAddress((void**)&y,    g_y);
    cudaGetSymbolAddress((void**)&hbuf, g_h);
    cudaGetSymbolAddress((void**)&tbuf, g_t);
    cudaGetSymbolAddress((void**)&x1,   g_x1);

    // 1) qkv = x @ w_attn + b_attn          (4096x1024 @ 1024x3072)
    gemm_bias_kernel<false><<<dim3(3 * CDIM / 128, ROWS / 128), 256>>>(
        x, w_attn, b_attn, qkv, ROWS, 3 * CDIM, CDIM);

    // 2) causal MHA -> y (B,T,C)
    attn_kernel<<<dim3(SEQ / 64, NHEAD, BATCH), 256>>>(qkv, y);

    // 3) h = gelu(y @ wa1 + ba1)            (4096x1024 @ 1024x4096)
    gemm_bias_kernel<true><<<dim3(HID / 128, ROWS / 128), 256>>>(
        y, wa1, ba1, hbuf, ROWS, HID, CDIM);

    // 4) t = h @ wa2 + ba2                  (4096x4096 @ 4096x1024)
    gemm_bias_kernel<false><<<dim3(CDIM / 128, ROWS / 128), 256>>>(
        hbuf, wa2, ba2, tbuf, ROWS, CDIM, HID);

    // 5) x1 = x + LN(t; g1, be1)
    add_ln_kernel<<<ROWS, 256>>>(x, tbuf, g1, be1, x1);

    // 6) h = gelu(x1 @ wf1 + bf1)
    gemm_bias_kernel<true><<<dim3(HID / 128, ROWS / 128), 256>>>(
        x1, wf1, bf1, hbuf, ROWS, HID, CDIM);

    // 7) t = h @ wf2 + bf2
    gemm_bias_kernel<false><<<dim3(CDIM / 128, ROWS / 128), 256>>>(
        hbuf, wf2, bf2, tbuf, ROWS, CDIM, HID);

    // 8) out = x1 + LN(t; g2, be2)
    add_ln_kernel<<<ROWS, 256>>>(x1, tbuf, g2, be2, out);
}

// round 3
// speedup vs baseline: 1.4371x; 1.4371x over previous
#include <cuda_runtime.h>
#include <cuda_bf16.h>
#include <math.h>
#include <stdint.h>

// Problem constants
#define BATCH 2
#define SEQ   2048
#define CDIM  1024
#define NHEAD 16
#define HDIM  64
#define ROWS  (BATCH * SEQ)          // 4096
#define HID   (4 * CDIM)             // 4096

typedef unsigned short u16;
typedef unsigned int   u32;

// ---------------- scratch (static device globals; no allocation) ----------------
__device__ float g_qkv[(size_t)ROWS * 3 * CDIM];
__device__ float g_t  [(size_t)ROWS * CDIM];
__device__ float g_x1 [(size_t)ROWS * CDIM];
__device__ u16 g_xh [(size_t)ROWS * CDIM],  g_xl [(size_t)ROWS * CDIM];
__device__ u16 g_yh [(size_t)ROWS * CDIM],  g_yl [(size_t)ROWS * CDIM];
__device__ u16 g_x1h[(size_t)ROWS * CDIM],  g_x1l[(size_t)ROWS * CDIM];
__device__ u16 g_hh [(size_t)ROWS * HID],   g_hl [(size_t)ROWS * HID];
__device__ u16 g_wah[(size_t)3*CDIM*CDIM], g_wal[(size_t)3*CDIM*CDIM];
__device__ u16 g_w1h[(size_t)HID*CDIM],    g_w1l[(size_t)HID*CDIM];
__device__ u16 g_w2h[(size_t)CDIM*HID],    g_w2l[(size_t)CDIM*HID];
__device__ u16 g_w3h[(size_t)HID*CDIM],    g_w3l[(size_t)HID*CDIM];
__device__ u16 g_w4h[(size_t)CDIM*HID],    g_w4l[(size_t)CDIM*HID];

// ---------------- helpers ----------------
__device__ __forceinline__ uint32_t smem_u32(const void* p) {
    uint32_t a;
    asm("{ .reg .u64 t; cvta.to.shared.u64 t, %1; cvt.u32.u64 %0, t; }" : "=r"(a) : "l"(p));
    return a;
}
__device__ __forceinline__ void cp16(uint32_t dst, const void* src) {
    asm volatile("cp.async.cg.shared.global [%0], [%1], 16;" :: "r"(dst), "l"(src) : "memory");
}
#define CP_COMMIT() asm volatile("cp.async.commit_group;" ::: "memory")

__device__ __forceinline__ void ldsm4(u32* r, u32 addr) {
    asm volatile("ldmatrix.sync.aligned.m8n8.x4.shared.b16 {%0,%1,%2,%3}, [%4];"
        : "=r"(r[0]), "=r"(r[1]), "=r"(r[2]), "=r"(r[3]) : "r"(addr));
}
__device__ __forceinline__ void mma_bf16(float* d, const u32* a, const u32* b) {
    asm volatile("mma.sync.aligned.m16n8k16.row.col.f32.bf16.bf16.f32 "
        "{%0,%1,%2,%3}, {%4,%5,%6,%7}, {%8,%9}, {%0,%1,%2,%3};"
        : "+f"(d[0]), "+f"(d[1]), "+f"(d[2]), "+f"(d[3])
        : "r"(a[0]), "r"(a[1]), "r"(a[2]), "r"(a[3]), "r"(b[0]), "r"(b[1]));
}
__device__ __forceinline__ uint32_t swz(uint32_t off) { return off ^ ((off >> 3) & 0x70); }

__device__ __forceinline__ u16 bf_hi(float v) { return __bfloat16_as_ushort(__float2bfloat16(v)); }
__device__ __forceinline__ u16 bf_lo(float v, u16 hb) {
    return __bfloat16_as_ushort(__float2bfloat16(v - __bfloat162float(__ushort_as_bfloat16(hb))));
}

// ---------------- decompose (elementwise) ----------------
__global__ __launch_bounds__(256) void decomp_k(const float* __restrict__ x,
                                                u16* __restrict__ h, u16* __restrict__ l, int n4) {
    int i = blockIdx.x * 256 + threadIdx.x;
    if (i >= n4) return;
    float4 v = ((const float4*)x)[i];
    u16 h0 = bf_hi(v.x), h1 = bf_hi(v.y), h2 = bf_hi(v.z), h3 = bf_hi(v.w);
    u16 l0 = bf_lo(v.x, h0), l1 = bf_lo(v.y, h1), l2 = bf_lo(v.z, h2), l3 = bf_lo(v.w, h3);
    ((uint2*)h)[i] = make_uint2((u32)h0 | ((u32)h1 << 16), (u32)h2 | ((u32)h3 << 16));
    ((uint2*)l)[i] = make_uint2((u32)l0 | ((u32)l1 << 16), (u32)l2 | ((u32)l3 << 16));
}

// ---------------- transpose + decompose weights: W[K][N] fp32 -> T[N][K] bf16 hi/lo ----------------
__global__ __launch_bounds__(256) void tdecomp_k(const float* __restrict__ W,
                                                 u16* __restrict__ Th, u16* __restrict__ Tl,
                                                 int K, int N) {
    __shared__ float t[32][33];
    const int n0 = blockIdx.x * 32, k0 = blockIdx.y * 32;
    const int tx = threadIdx.x, ty = threadIdx.y;  // 32x8
    #pragma unroll
    for (int i = 0; i < 32; i += 8)
        t[ty + i][tx] = W[(size_t)(k0 + ty + i) * N + n0 + tx];
    __syncthreads();
    #pragma unroll
    for (int i = 0; i < 32; i += 8) {
        float v = t[tx][ty + i];
        size_t o = (size_t)(n0 + ty + i) * K + k0 + tx;
        u16 hb = bf_hi(v);
        Th[o] = hb;
        Tl[o] = bf_lo(v, hb);
    }
}

// ---------------- tensor-core GEMM via mma.sync: C = act(A @ B^T + bias) ----------------
// A: [M][K] bf16 hi/lo (K-major). B: [N][K] bf16 hi/lo. bf16x3 accumulation in fp32 regs.
// CTA 128x128, BK=64, 8 warps (warp tile 32x64), cp.async double buffer.
// OUT=0: fp32 C. OUT=1: gelu -> bf16 hi/lo pair.
#define BK 64
#define STAGE_B 65536               // 4 tiles x 128 x 64 x 2B
#define MG_SMEM (2 * STAGE_B)       // 128 KB

template<int OUT>
__global__ __launch_bounds__(256, 1) void mma_gemm(
    const u16* __restrict__ Ahi, const u16* __restrict__ Alo,
    const u16* __restrict__ Bhi, const u16* __restrict__ Blo,
    const float* __restrict__ bias,
    float* __restrict__ C, u16* __restrict__ Chi, u16* __restrict__ Clo,
    int N, int K)
{
    extern __shared__ char smem_raw[];
    const uint32_t sbase = smem_u32(smem_raw);

    const int tid = threadIdx.x, lane = tid & 31, wid = tid >> 5;
    const int warp_m = wid & 3, warp_n = wid >> 2;
    const int bm = blockIdx.y * 128, bn = blockIdx.x * 128;

    const u16* aH = Ahi + (size_t)bm * K;
    const u16* aL = Alo + (size_t)bm * K;
    const u16* bH = Bhi + (size_t)bn * K;
    const u16* bL = Blo + (size_t)bn * K;

    // cp.async mapping: 1024 16B segs per 16KB tile; thread does 4 segs/tile
    const int nk = K / BK;

    auto load_stage = [&](int t) {
        const uint32_t st = sbase + (uint32_t)(t & 1) * STAGE_B;
        const int k0 = t * BK;
        #pragma unroll
        for (int i = 0; i < 4; ++i) {
            const int idx = i * 256 + tid;
            const int row = idx >> 3, seg = idx & 7;
            const uint32_t soff = swz((uint32_t)(row * 128 + seg * 16));
            const size_t goff = (size_t)row * K + k0 + seg * 8;
            cp16(st + soff,         aH + goff);
            cp16(st + 16384 + soff, aL + goff);
            cp16(st + 32768 + soff, bH + goff);
            cp16(st + 49152 + soff, bL + goff);
        }
        CP_COMMIT();
    };

    float acc[2][8][4];
    #pragma unroll
    for (int mi = 0; mi < 2; ++mi)
        #pragma unroll
        for (int ni = 0; ni < 8; ++ni)
            #pragma unroll
            for (int j = 0; j < 4; ++j) acc[mi][ni][j] = 0.f;

    load_stage(0);

    for (int t = 0; t < nk; ++t) {
        if (t + 1 < nk) {
            load_stage(t + 1);
            asm volatile("cp.async.wait_group 1;" ::: "memory");
        } else {
            asm volatile("cp.async.wait_group 0;" ::: "memory");
        }
        __syncthreads();

        const uint32_t st = sbase + (uint32_t)(t & 1) * STAGE_B;
        // per-lane ldmatrix row addressing
        const int lrow = lane & 15;          // row within 16-row group
        const int kblk = lane >> 4;          // 0/1 -> k 0-7 / 8-15

        #pragma unroll
        for (int s = 0; s < BK / 16; ++s) {
            const int c16 = s * 2 + kblk;    // 16B column index
            u32 a_hi[2][4], a_lo[2][4];
            #pragma unroll
            for (int mi = 0; mi < 2; ++mi) {
                const int row = warp_m * 32 + mi * 16 + lrow;
                const uint32_t off = swz((uint32_t)(row * 128 + c16 * 16));
                ldsm4(a_hi[mi], st + off);
                ldsm4(a_lo[mi], st + 16384 + off);
            }
            u32 b_hi[8][2], b_lo[8][2];
            #pragma unroll
            for (int nb = 0; nb < 4; ++nb) {
                const int row = warp_n * 64 + nb * 16 + lrow;
                const uint32_t off = swz((uint32_t)(row * 128 + c16 * 16));
                u32 r[4];
                ldsm4(r, st + 32768 + off);
                b_hi[nb * 2][0] = r[0]; b_hi[nb * 2 + 1][0] = r[1];
                b_hi[nb * 2][1] = r[2]; b_hi[nb * 2 + 1][1] = r[3];
                ldsm4(r, st + 49152 + off);
                b_lo[nb * 2][0] = r[0]; b_lo[nb * 2 + 1][0] = r[1];
                b_lo[nb * 2][1] = r[2]; b_lo[nb * 2 + 1][1] = r[3];
            }
            #pragma unroll
            for (int mi = 0; mi < 2; ++mi)
                #pragma unroll
                for (int ni = 0; ni < 8; ++ni) {
                    mma_bf16(acc[mi][ni], a_hi[mi], b_hi[ni]);
                    mma_bf16(acc[mi][ni], a_hi[mi], b_lo[ni]);
                    mma_bf16(acc[mi][ni], a_lo[mi], b_hi[ni]);
                }
        }
        __syncthreads();
    }

    // epilogue: frag (mi, ni): rows bm+warp_m*32+mi*16+(lane>>2)(+8), cols bn+warp_n*64+ni*8+(lane&3)*2
    #pragma unroll
    for (int ni = 0; ni < 8; ++ni) {
        const int col = bn + warp_n * 64 + ni * 8 + (lane & 3) * 2;
        const float b0 = bias[col], b1 = bias[col + 1];
        #pragma unroll
        for (int mi = 0; mi < 2; ++mi) {
            const int r0 = bm + warp_m * 32 + mi * 16 + (lane >> 2);
            #pragma unroll
            for (int half = 0; half < 2; ++half) {
                const int r = r0 + half * 8;
                float v0 = acc[mi][ni][half * 2 + 0] + b0;
                float v1 = acc[mi][ni][half * 2 + 1] + b1;
                if (OUT == 0) {
                    *(float2*)(C + (size_t)r * N + col) = make_float2(v0, v1);
                } else {
                    v0 *= normcdff(v0);
                    v1 *= normcdff(v1);
                    u16 h0 = bf_hi(v0), h1 = bf_hi(v1);
                    u16 l0 = bf_lo(v0, h0), l1 = bf_lo(v1, h1);
                    *(u32*)(Chi + (size_t)r * N + col) = (u32)h0 | ((u32)h1 << 16);
                    *(u32*)(Clo + (size_t)r * N + col) = (u32)l0 | ((u32)l1 << 16);
                }
            }
        }
    }
}

// ---------------- Flash attention (causal), qkv split order K|Q|V ----------------
__global__ __launch_bounds__(256) void attn_kernel(
    const float* __restrict__ qkv, u16* __restrict__ yh, u16* __restrict__ yl)
{
    const int b = blockIdx.z;
    const int h = blockIdx.y;
    const int q0 = blockIdx.x * 64;
    const int tid = threadIdx.x;
    const int q = tid >> 2;
    const int dseg = (tid & 3) * 16;

    __shared__ float Ks[64][64];
    __shared__ float Vs[64][64];

    float Qr[16];
    {
        const float* qptr = qkv + ((size_t)b * SEQ + (q0 + q)) * (3 * CDIM)
                            + CDIM + h * HDIM + dseg;
        #pragma unroll
        for (int i = 0; i < 16; i += 4)
            *(float4*)&Qr[i] = *(const float4*)(qptr + i);
    }

    float m = -INFINITY, l = 0.f;
    float o[16];
    #pragma unroll
    for (int j = 0; j < 16; ++j) o[j] = 0.f;

    const int ld_row = tid >> 2;
    const int ld_col = (tid & 3) * 16;

    const int ntiles = q0 / 64 + 1;
    for (int kt = 0; kt < ntiles; ++kt) {
        const int k0 = kt * 64;
        const float* kbase = qkv + ((size_t)b * SEQ + (k0 + ld_row)) * (3 * CDIM)
                             + h * HDIM + ld_col;
        const float* vbase = kbase + 2 * CDIM;
        __syncthreads();
        #pragma unroll
        for (int i = 0; i < 16; i += 4) {
            *(float4*)&Ks[ld_row][ld_col + i] = *(const float4*)(kbase + i);
            *(float4*)&Vs[ld_row][ld_col + i] = *(const float4*)(vbase + i);
        }
        __syncthreads();

        float s[64];
        #pragma unroll
        for (int k = 0; k < 64; ++k) {
            float a = 0.f;
            #pragma unroll
            for (int j = 0; j < 16; j += 4) {
                float4 kv = *(const float4*)&Ks[k][dseg + j];
                a = fmaf(Qr[j + 0], kv.x, a);
                a = fmaf(Qr[j + 1], kv.y, a);
                a = fmaf(Qr[j + 2], kv.z, a);
                a = fmaf(Qr[j + 3], kv.w, a);
            }
            s[k] = a;
        }
        #pragma unroll
        for (int k = 0; k < 64; ++k) {
            float v = s[k];
            v += __shfl_xor_sync(0xffffffffu, v, 1);
            v += __shfl_xor_sync(0xffffffffu, v, 2);
            s[k] = v * 0.125f;
        }
        if (k0 + 63 > q0 + q) {
            #pragma unroll
            for (int k = 0; k < 64; ++k)
                if (k0 + k > q0 + q) s[k] = -INFINITY;
        }
        float mt = -INFINITY;
        #pragma unroll
        for (int k = 0; k < 64; ++k) mt = fmaxf(mt, s[k]);
        const float mn = fmaxf(m, mt);
        const float scale = __expf(m - mn);
        float ls = 0.f;
        #pragma unroll
        for (int k = 0; k < 64; ++k) {
            const float p = __expf(s[k] - mn);
            s[k] = p;
            ls += p;
        }
        l = l * scale + ls;
        m = mn;
        #pragma unroll
        for (int j = 0; j < 16; ++j) o[j] *= scale;
        #pragma unroll
        for (int k = 0; k < 64; ++k) {
            const float p = s[k];
            #pragma unroll
            for (int j = 0; j < 16; j += 4) {
                float4 vv = *(const float4*)&Vs[k][dseg + j];
                o[j + 0] = fmaf(p, vv.x, o[j + 0]);
                o[j + 1] = fmaf(p, vv.y, o[j + 1]);
                o[j + 2] = fmaf(p, vv.z, o[j + 2]);
                o[j + 3] = fmaf(p, vv.w, o[j + 3]);
            }
        }
    }

    const float rl = 1.f / l;
    const size_t base = ((size_t)b * SEQ + (q0 + q)) * CDIM + h * HDIM + dseg;
    #pragma unroll
    for (int j = 0; j < 16; j += 2) {
        float v0 = o[j] * rl, v1 = o[j + 1] * rl;
        u16 h0 = bf_hi(v0), h1 = bf_hi(v1);
        u16 l0 = bf_lo(v0, h0), l1 = bf_lo(v1, h1);
        *(u32*)(yh + base + j) = (u32)h0 | ((u32)h1 << 16);
        *(u32*)(yl + base + j) = (u32)l0 | ((u32)l1 << 16);
    }
}

// ---------------- residual + LayerNorm ----------------
__device__ __forceinline__ float block_sum256(float v, float* red) {
    const int lane = threadIdx.x & 31;
    const int w = threadIdx.x >> 5;
    #pragma unroll
    for (int off = 16; off; off >>= 1) v += __shfl_xor_sync(0xffffffffu, v, off);
    if (lane == 0) red[w] = v;
    __syncthreads();
    float t = (threadIdx.x < 8) ? red[threadIdx.x] : 0.f;
    if (w == 0) {
        t += __shfl_xor_sync(0xffffffffu, t, 4);
        t += __shfl_xor_sync(0xffffffffu, t, 2);
        t += __shfl_xor_sync(0xffffffffu, t, 1);
        if (lane == 0) red[0] = t;
    }
    __syncthreads();
    const float r = red[0];
    __syncthreads();
    return r;
}

template<bool PAIR>
__global__ __launch_bounds__(256) void add_ln_kernel(
    const float* __restrict__ xres, const float* __restrict__ v,
    const float* __restrict__ g, const float* __restrict__ be,
    float* __restrict__ out, u16* __restrict__ oh, u16* __restrict__ ol)
{
    __shared__ float red[8];
    const size_t row = blockIdx.x;
    const int c0 = threadIdx.x * 4;
    const float* vr = v + row * CDIM;

    float vals[4];
    *(float4*)vals = *(const float4*)(vr + c0);
    float s = vals[0] + vals[1] + vals[2] + vals[3];
    const float mean = block_sum256(s, red) * (1.f / CDIM);

    float d2 = 0.f;
    #pragma unroll
    for (int i = 0; i < 4; ++i) {
        const float d = vals[i] - mean;
        d2 = fmaf(d, d, d2);
    }
    const float var = block_sum256(d2, red) * (1.f / CDIM);
    const float rstd = rsqrtf(var + 1e-5f);

    float4 xr = *(const float4*)(xres + row * CDIM + c0);
    float4 gg = *(const float4*)(g + c0);
    float4 bb = *(const float4*)(be + c0);
    float4 res;
    res.x = xr.x + (vals[0] - mean) * rstd * gg.x + bb.x;
    res.y = xr.y + (vals[1] - mean) * rstd * gg.y + bb.y;
    res.z = xr.z + (vals[2] - mean) * rstd * gg.z + bb.z;
    res.w = xr.w + (vals[3] - mean) * rstd * gg.w + bb.w;
    *(float4*)(out + row * CDIM + c0) = res;
    if (PAIR) {
        u16 h0 = bf_hi(res.x), h1 = bf_hi(res.y), h2 = bf_hi(res.z), h3 = bf_hi(res.w);
        u16 l0 = bf_lo(res.x, h0), l1 = bf_lo(res.y, h1), l2 = bf_lo(res.z, h2), l3 = bf_lo(res.w, h3);
        *(uint2*)(oh + row * CDIM + c0) = make_uint2((u32)h0 | ((u32)h1 << 16), (u32)h2 | ((u32)h3 << 16));
        *(uint2*)(ol + row * CDIM + c0) = make_uint2((u32)l0 | ((u32)l1 << 16), (u32)l2 | ((u32)l3 << 16));
    }
}

// ---------------- launch ----------------
extern "C" void kernel_launch(void* const* d_in, const int* in_sizes, int n_in,
                              void* d_out, int out_size)
{
    const float* x      = (const float*)d_in[0];
    const float* w_attn = (const float*)d_in[1];
    const float* b_attn = (const float*)d_in[2];
    const float* wa1    = (const float*)d_in[3];
    const float* ba1    = (const float*)d_in[4];
    const float* wa2    = (const float*)d_in[5];
    const float* ba2    = (const float*)d_in[6];
    const float* g1     = (const float*)d_in[7];
    const float* be1    = (const float*)d_in[8];
    const float* wf1    = (const float*)d_in[9];
    const float* bf1    = (const float*)d_in[10];
    const float* wf2    = (const float*)d_in[11];
    const float* bf2    = (const float*)d_in[12];
    const float* g2     = (const float*)d_in[13];
    const float* be2    = (const float*)d_in[14];
    float* out = (float*)d_out;

    float *qkv, *tbuf, *x1;
    u16 *xh, *xl, *yh, *yl, *x1h, *x1l, *hh, *hl;
    u16 *wah, *wal, *w1h, *w1l, *w2h, *w2l, *w3h, *w3l, *w4h, *w4l;
    cudaGetSymbolAddress((void**)&qkv, g_qkv);
    cudaGetSymbolAddress((void**)&tbuf, g_t);
    cudaGetSymbolAddress((void**)&x1, g_x1);
    cudaGetSymbolAddress((void**)&xh, g_xh);   cudaGetSymbolAddress((void**)&xl, g_xl);
    cudaGetSymbolAddress((void**)&yh, g_yh);   cudaGetSymbolAddress((void**)&yl, g_yl);
    cudaGetSymbolAddress((void**)&x1h, g_x1h); cudaGetSymbolAddress((void**)&x1l, g_x1l);
    cudaGetSymbolAddress((void**)&hh, g_hh);   cudaGetSymbolAddress((void**)&hl, g_hl);
    cudaGetSymbolAddress((void**)&wah, g_wah); cudaGetSymbolAddress((void**)&wal, g_wal);
    cudaGetSymbolAddress((void**)&w1h, g_w1h); cudaGetSymbolAddress((void**)&w1l, g_w1l);
    cudaGetSymbolAddress((void**)&w2h, g_w2h); cudaGetSymbolAddress((void**)&w2l, g_w2l);
    cudaGetSymbolAddress((void**)&w3h, g_w3h); cudaGetSymbolAddress((void**)&w3l, g_w3l);
    cudaGetSymbolAddress((void**)&w4h, g_w4h); cudaGetSymbolAddress((void**)&w4l, g_w4l);

    cudaFuncSetAttribute(mma_gemm<0>, cudaFuncAttributeMaxDynamicSharedMemorySize, MG_SMEM);
    cudaFuncSetAttribute(mma_gemm<1>, cudaFuncAttributeMaxDynamicSharedMemorySize, MG_SMEM);

    const dim3 tb(32, 8);
    tdecomp_k<<<dim3(3 * CDIM / 32, CDIM / 32), tb>>>(w_attn, wah, wal, CDIM, 3 * CDIM);
    tdecomp_k<<<dim3(HID / 32, CDIM / 32), tb>>>(wa1, w1h, w1l, CDIM, HID);
    tdecomp_k<<<dim3(CDIM / 32, HID / 32), tb>>>(wa2, w2h, w2l, HID, CDIM);
    tdecomp_k<<<dim3(HID / 32, CDIM / 32), tb>>>(wf1, w3h, w3l, CDIM, HID);
    tdecomp_k<<<dim3(CDIM / 32, HID / 32), tb>>>(wf2, w4h, w4l, HID, CDIM);
    decomp_k<<<(ROWS * CDIM / 4 + 255) / 256, 256>>>(x, xh, xl, ROWS * CDIM / 4);

    // 1) qkv = x @ w_attn + b_attn  (fp32 out)
    mma_gemm<0><<<dim3(3 * CDIM / 128, ROWS / 128), 256, MG_SMEM>>>(
        xh, xl, wah, wal, b_attn, qkv, nullptr, nullptr, 3 * CDIM, CDIM);

    // 2) causal MHA -> y hi/lo
    attn_kernel<<<dim3(SEQ / 64, NHEAD, BATCH), 256>>>(qkv, yh, yl);

    // 3) h = gelu(y @ wa1 + ba1) -> bf16 hi/lo
    mma_gemm<1><<<dim3(HID / 128, ROWS / 128), 256, MG_SMEM>>>(
        yh, yl, w1h, w1l, ba1, nullptr, hh, hl, HID, CDIM);

    // 4) t = h @ wa2 + ba2 (fp32)
    mma_gemm<0><<<dim3(CDIM / 128, ROWS / 128), 256, MG_SMEM>>>(
        hh, hl, w2h, w2l, ba2, tbuf, nullptr, nullptr, CDIM, HID);

    // 5) x1 = x + LN(t) (fp32 + hi/lo)
    add_ln_kernel<true><<<ROWS, 256>>>(x, tbuf, g1, be1, x1, x1h, x1l);

    // 6) h = gelu(x1 @ wf1 + bf1) -> bf16 hi/lo
    mma_gemm<1><<<dim3(HID / 128, ROWS / 128), 256, MG_SMEM>>>(
        x1h, x1l, w3h, w3l, bf1, nullptr, hh, hl, HID, CDIM);

    // 7) t = h @ wf2 + bf2 (fp32)
    mma_gemm<0><<<dim3(CDIM / 128, ROWS / 128), 256, MG_SMEM>>>(
        hh, hl, w4h, w4l, bf2, tbuf, nullptr, nullptr, CDIM, HID);

    // 8) out = x1 + LN(t)
    add_ln_kernel<false><<<ROWS, 256>>>(x1, tbuf, g2, be2, out, nullptr, nullptr);
}

// round 4
// speedup vs baseline: 3.1951x; 2.2233x over previous
#include <cuda_runtime.h>
#include <cuda_bf16.h>
#include <math.h>
#include <stdint.h>

// Problem constants
#define BATCH 2
#define SEQ   2048
#define CDIM  1024
#define NHEAD 16
#define HDIM  64
#define ROWS  (BATCH * SEQ)          // 4096
#define HID   (4 * CDIM)             // 4096

typedef unsigned short u16;
typedef unsigned int   u32;

// ---------------- scratch (static device globals; no allocation) ----------------
__device__ float g_t  [(size_t)ROWS * CDIM];
__device__ float g_x1 [(size_t)ROWS * CDIM];
__device__ u16 g_xh [(size_t)ROWS * CDIM],  g_xl [(size_t)ROWS * CDIM];
__device__ u16 g_qkvh[(size_t)ROWS * 3 * CDIM], g_qkvl[(size_t)ROWS * 3 * CDIM];
__device__ u16 g_yh [(size_t)ROWS * CDIM],  g_yl [(size_t)ROWS * CDIM];
__device__ u16 g_x1h[(size_t)ROWS * CDIM],  g_x1l[(size_t)ROWS * CDIM];
__device__ u16 g_hh [(size_t)ROWS * HID],   g_hl [(size_t)ROWS * HID];
__device__ u16 g_wah[(size_t)3*CDIM*CDIM], g_wal[(size_t)3*CDIM*CDIM];
__device__ u16 g_w1h[(size_t)HID*CDIM],    g_w1l[(size_t)HID*CDIM];
__device__ u16 g_w2h[(size_t)CDIM*HID],    g_w2l[(size_t)CDIM*HID];
__device__ u16 g_w3h[(size_t)HID*CDIM],    g_w3l[(size_t)HID*CDIM];
__device__ u16 g_w4h[(size_t)CDIM*HID],    g_w4l[(size_t)CDIM*HID];

// ---------------- helpers ----------------
__device__ __forceinline__ uint32_t smem_u32(const void* p) {
    uint32_t a;
    asm("{ .reg .u64 t; cvta.to.shared.u64 t, %1; cvt.u32.u64 %0, t; }" : "=r"(a) : "l"(p));
    return a;
}
__device__ __forceinline__ void cp16(uint32_t dst, const void* src) {
    asm volatile("cp.async.cg.shared.global [%0], [%1], 16;" :: "r"(dst), "l"(src) : "memory");
}
#define CP_COMMIT() asm volatile("cp.async.commit_group;" ::: "memory")

__device__ __forceinline__ void ldsm4(u32* r, u32 addr) {
    asm volatile("ldmatrix.sync.aligned.m8n8.x4.shared.b16 {%0,%1,%2,%3}, [%4];"
        : "=r"(r[0]), "=r"(r[1]), "=r"(r[2]), "=r"(r[3]) : "r"(addr));
}
__device__ __forceinline__ void ldsm4t(u32* r, u32 addr) {
    asm volatile("ldmatrix.sync.aligned.m8n8.x4.trans.shared.b16 {%0,%1,%2,%3}, [%4];"
        : "=r"(r[0]), "=r"(r[1]), "=r"(r[2]), "=r"(r[3]) : "r"(addr));
}
__device__ __forceinline__ void mma_bf16(float* d, const u32* a, const u32* b) {
    asm volatile("mma.sync.aligned.m16n8k16.row.col.f32.bf16.bf16.f32 "
        "{%0,%1,%2,%3}, {%4,%5,%6,%7}, {%8,%9}, {%0,%1,%2,%3};"
        : "+f"(d[0]), "+f"(d[1]), "+f"(d[2]), "+f"(d[3])
        : "r"(a[0]), "r"(a[1]), "r"(a[2]), "r"(a[3]), "r"(b[0]), "r"(b[1]));
}
__device__ __forceinline__ uint32_t swz(uint32_t off) { return off ^ ((off >> 3) & 0x70); }

__device__ __forceinline__ u16 bf_hi(float v) { return __bfloat16_as_ushort(__float2bfloat16(v)); }
__device__ __forceinline__ u16 bf_lo(float v, u16 hb) {
    return __bfloat16_as_ushort(__float2bfloat16(v - __bfloat162float(__ushort_as_bfloat16(hb))));
}

// ---------------- decompose (elementwise) ----------------
__global__ __launch_bounds__(256) void decomp_k(const float* __restrict__ x,
                                                u16* __restrict__ h, u16* __restrict__ l, int n4) {
    int i = blockIdx.x * 256 + threadIdx.x;
    if (i >= n4) return;
    float4 v = ((const float4*)x)[i];
    u16 h0 = bf_hi(v.x), h1 = bf_hi(v.y), h2 = bf_hi(v.z), h3 = bf_hi(v.w);
    u16 l0 = bf_lo(v.x, h0), l1 = bf_lo(v.y, h1), l2 = bf_lo(v.z, h2), l3 = bf_lo(v.w, h3);
    ((uint2*)h)[i] = make_uint2((u32)h0 | ((u32)h1 << 16), (u32)h2 | ((u32)h3 << 16));
    ((uint2*)l)[i] = make_uint2((u32)l0 | ((u32)l1 << 16), (u32)l2 | ((u32)l3 << 16));
}

// ---------------- transpose + decompose weights: W[K][N] fp32 -> T[N][K] bf16 hi/lo ----------------
__global__ __launch_bounds__(256) void tdecomp_k(const float* __restrict__ W,
                                                 u16* __restrict__ Th, u16* __restrict__ Tl,
                                                 int K, int N) {
    __shared__ float t[32][33];
    const int n0 = blockIdx.x * 32, k0 = blockIdx.y * 32;
    const int tx = threadIdx.x, ty = threadIdx.y;  // 32x8
    #pragma unroll
    for (int i = 0; i < 32; i += 8)
        t[ty + i][tx] = W[(size_t)(k0 + ty + i) * N + n0 + tx];
    __syncthreads();
    #pragma unroll
    for (int i = 0; i < 32; i += 8) {
        float v = t[tx][ty + i];
        size_t o = (size_t)(n0 + ty + i) * K + k0 + tx;
        u16 hb = bf_hi(v);
        Th[o] = hb;
        Tl[o] = bf_lo(v, hb);
    }
}

// ---------------- tensor-core GEMM via mma.sync ----------------
// OUT=0: fp32 C. OUT=1: gelu -> bf16 hi/lo. OUT=2: bf16 hi/lo (no gelu).
#define BK 64
#define STAGE_B 65536
#define MG_SMEM (2 * STAGE_B)

template<int OUT>
__global__ __launch_bounds__(256, 1) void mma_gemm(
    const u16* __restrict__ Ahi, const u16* __restrict__ Alo,
    const u16* __restrict__ Bhi, const u16* __restrict__ Blo,
    const float* __restrict__ bias,
    float* __restrict__ C, u16* __restrict__ Chi, u16* __restrict__ Clo,
    int N, int K)
{
    extern __shared__ char smem_raw[];
    const uint32_t sbase = smem_u32(smem_raw);

    const int tid = threadIdx.x, lane = tid & 31, wid = tid >> 5;
    const int warp_m = wid & 3, warp_n = wid >> 2;
    const int bm = blockIdx.y * 128, bn = blockIdx.x * 128;

    const u16* aH = Ahi + (size_t)bm * K;
    const u16* aL = Alo + (size_t)bm * K;
    const u16* bH = Bhi + (size_t)bn * K;
    const u16* bL = Blo + (size_t)bn * K;

    const int nk = K / BK;

    auto load_stage = [&](int t) {
        const uint32_t st = sbase + (uint32_t)(t & 1) * STAGE_B;
        const int k0 = t * BK;
        #pragma unroll
        for (int i = 0; i < 4; ++i) {
            const int idx = i * 256 + tid;
            const int row = idx >> 3, seg = idx & 7;
            const uint32_t soff = swz((uint32_t)(row * 128 + seg * 16));
            const size_t goff = (size_t)row * K + k0 + seg * 8;
            cp16(st + soff,         aH + goff);
            cp16(st + 16384 + soff, aL + goff);
            cp16(st + 32768 + soff, bH + goff);
            cp16(st + 49152 + soff, bL + goff);
        }
        CP_COMMIT();
    };

    float acc[2][8][4];
    #pragma unroll
    for (int mi = 0; mi < 2; ++mi)
        #pragma unroll
        for (int ni = 0; ni < 8; ++ni)
            #pragma unroll
            for (int j = 0; j < 4; ++j) acc[mi][ni][j] = 0.f;

    load_stage(0);

    for (int t = 0; t < nk; ++t) {
        if (t + 1 < nk) {
            load_stage(t + 1);
            asm volatile("cp.async.wait_group 1;" ::: "memory");
        } else {
            asm volatile("cp.async.wait_group 0;" ::: "memory");
        }
        __syncthreads();

        const uint32_t st = sbase + (uint32_t)(t & 1) * STAGE_B;
        const int lrow = lane & 15;
        const int kblk = lane >> 4;

        #pragma unroll
        for (int s = 0; s < BK / 16; ++s) {
            const int c16 = s * 2 + kblk;
            u32 a_hi[2][4], a_lo[2][4];
            #pragma unroll
            for (int mi = 0; mi < 2; ++mi) {
                const int row = warp_m * 32 + mi * 16 + lrow;
                const uint32_t off = swz((uint32_t)(row * 128 + c16 * 16));
                ldsm4(a_hi[mi], st + off);
                ldsm4(a_lo[mi], st + 16384 + off);
            }
            u32 b_hi[8][2], b_lo[8][2];
            #pragma unroll
            for (int nb = 0; nb < 4; ++nb) {
                const int row = warp_n * 64 + nb * 16 + lrow;
                const uint32_t off = swz((uint32_t)(row * 128 + c16 * 16));
                u32 r[4];
                ldsm4(r, st + 32768 + off);
                b_hi[nb * 2][0] = r[0]; b_hi[nb * 2 + 1][0] = r[1];
                b_hi[nb * 2][1] = r[2]; b_hi[nb * 2 + 1][1] = r[3];
                ldsm4(r, st + 49152 + off);
                b_lo[nb * 2][0] = r[0]; b_lo[nb * 2 + 1][0] = r[1];
                b_lo[nb * 2][1] = r[2]; b_lo[nb * 2 + 1][1] = r[3];
            }
            #pragma unroll
            for (int mi = 0; mi < 2; ++mi)
                #pragma unroll
                for (int ni = 0; ni < 8; ++ni) {
                    mma_bf16(acc[mi][ni], a_hi[mi], b_hi[ni]);
                    mma_bf16(acc[mi][ni], a_hi[mi], b_lo[ni]);
                    mma_bf16(acc[mi][ni], a_lo[mi], b_hi[ni]);
                }
        }
        __syncthreads();
    }

    #pragma unroll
    for (int ni = 0; ni < 8; ++ni) {
        const int col = bn + warp_n * 64 + ni * 8 + (lane & 3) * 2;
        const float b0 = bias[col], b1 = bias[col + 1];
        #pragma unroll
        for (int mi = 0; mi < 2; ++mi) {
            const int r0 = bm + warp_m * 32 + mi * 16 + (lane >> 2);
            #pragma unroll
            for (int half = 0; half < 2; ++half) {
                const int r = r0 + half * 8;
                float v0 = acc[mi][ni][half * 2 + 0] + b0;
                float v1 = acc[mi][ni][half * 2 + 1] + b1;
                if (OUT == 0) {
                    *(float2*)(C + (size_t)r * N + col) = make_float2(v0, v1);
                } else {
                    if (OUT == 1) {
                        v0 *= normcdff(v0);
                        v1 *= normcdff(v1);
                    }
                    u16 h0 = bf_hi(v0), h1 = bf_hi(v1);
                    u16 l0 = bf_lo(v0, h0), l1 = bf_lo(v1, h1);
                    *(u32*)(Chi + (size_t)r * N + col) = (u32)h0 | ((u32)h1 << 16);
                    *(u32*)(Clo + (size_t)r * N + col) = (u32)l0 | ((u32)l1 << 16);
                }
            }
        }
    }
}

// ---------------- tensor-core flash attention (causal), qkv split K|Q|V ----------------
// Block: 128 threads (4 warps), 64 queries; warp w owns query rows w*16..w*16+15.
// smem: Qh(8K) Ql(8K) | 2 stages x { Kh Kl Vh Vl } (8K each)
#define ATT_SMEM (16384 + 2 * 32768)   // 80 KB

__global__ __launch_bounds__(128) void attn_mma(
    const u16* __restrict__ qkvh, const u16* __restrict__ qkvl,
    u16* __restrict__ yh, u16* __restrict__ yl)
{
    extern __shared__ char smem_raw[];
    const uint32_t sb = smem_u32(smem_raw);
    const int tid = threadIdx.x, lane = tid & 31, wid = tid >> 5;
    const int qt = blockIdx.x, h = blockIdx.y, b = blockIdx.z;
    const int q0 = qt * 64;
    const int gid = lane >> 2, qp = lane & 3;
    const size_t tokbase = (size_t)b * SEQ;
    const int rs = 3 * CDIM;

    // Q hi/lo load (channel CDIM + h*64)
    #pragma unroll
    for (int i = 0; i < 4; ++i) {
        const int idx = i * 128 + tid;
        const int row = idx >> 3, seg = idx & 7;
        const uint32_t off = swz((uint32_t)(row * 128 + seg * 16));
        const size_t g = (tokbase + q0 + row) * rs + CDIM + h * HDIM + seg * 8;
        cp16(sb + off,        qkvh + g);
        cp16(sb + 8192 + off, qkvl + g);
    }

    auto load_stage = [&](int t) {
        const uint32_t st = sb + 16384 + (uint32_t)(t & 1) * 32768u;
        const int k0 = t * 64;
        #pragma unroll
        for (int i = 0; i < 4; ++i) {
            const int idx = i * 128 + tid;
            const int row = idx >> 3, seg = idx & 7;
            const uint32_t off = swz((uint32_t)(row * 128 + seg * 16));
            const size_t gk = (tokbase + k0 + row) * rs + h * HDIM + seg * 8;  // K at ch 0
            const size_t gv = gk + 2 * CDIM;                                   // V at ch 2C
            cp16(st + off,         qkvh + gk);
            cp16(st + 8192 + off,  qkvl + gk);
            cp16(st + 16384 + off, qkvh + gv);
            cp16(st + 24576 + off, qkvl + gv);
        }
        CP_COMMIT();
    };
    load_stage(0);  // Q cp16s ride in this group

    float m0 = -INFINITY, m1 = -INFINITY, l0 = 0.f, l1 = 0.f;
    float oacc[8][4];
    #pragma unroll
    for (int ni = 0; ni < 8; ++ni)
        #pragma unroll
        for (int j = 0; j < 4; ++j) oacc[ni][j] = 0.f;

    const int lr = lane & 15, ck = lane >> 4;
    const int ntiles = qt + 1;

    for (int t = 0; t < ntiles; ++t) {
        if (t + 1 < ntiles) {
            load_stage(t + 1);
            asm volatile("cp.async.wait_group 1;" ::: "memory");
        } else {
            asm volatile("cp.async.wait_group 0;" ::: "memory");
        }
        __syncthreads();
        const uint32_t st = sb + 16384 + (uint32_t)(t & 1) * 32768u;

        // ---- S = Q K^T (bf16x3) ----
        float sacc[8][4];
        #pragma unroll
        for (int ni = 0; ni < 8; ++ni)
            #pragma unroll
            for (int j = 0; j < 4; ++j) sacc[ni][j] = 0.f;

        #pragma unroll
        for (int s = 0; s < 4; ++s) {
            const int c16 = s * 2 + ck;
            u32 aH[4], aL[4];
            {
                const uint32_t off = swz((uint32_t)((wid * 16 + lr) * 128 + c16 * 16));
                ldsm4(aH, sb + off);
                ldsm4(aL, sb + 8192 + off);
            }
            u32 bH[8][2], bL[8][2];
            #pragma unroll
            for (int ng = 0; ng < 4; ++ng) {
                const uint32_t off = swz((uint32_t)((ng * 16 + lr) * 128 + c16 * 16));
                u32 r[4];
                ldsm4(r, st + off);
                bH[2 * ng][0] = r[0]; bH[2 * ng + 1][0] = r[1];
                bH[2 * ng][1] = r[2]; bH[2 * ng + 1][1] = r[3];
                ldsm4(r, st + 8192 + off);
                bL[2 * ng][0] = r[0]; bL[2 * ng + 1][0] = r[1];
                bL[2 * ng][1] = r[2]; bL[2 * ng + 1][1] = r[3];
            }
            #pragma unroll
            for (int ni = 0; ni < 8; ++ni) {
                mma_bf16(sacc[ni], aH, bH[ni]);
                mma_bf16(sacc[ni], aH, bL[ni]);
                mma_bf16(sacc[ni], aL, bH[ni]);
            }
        }
        #pragma unroll
        for (int ni = 0; ni < 8; ++ni)
            #pragma unroll
            for (int j = 0; j < 4; ++j) sacc[ni][j] *= 0.125f;

        // causal mask on the diagonal tile
        if (t == qt) {
            const int qr0 = q0 + wid * 16 + gid;
            #pragma unroll
            for (int ni = 0; ni < 8; ++ni) {
                const int kbase = t * 64 + ni * 8 + qp * 2;
                #pragma unroll
                for (int j = 0; j < 4; ++j) {
                    if (kbase + (j & 1) > qr0 + (j >> 1) * 8) sacc[ni][j] = -INFINITY;
                }
            }
        }

        // ---- online softmax (row halves: regs 0,1 -> row gid; 2,3 -> gid+8) ----
        float mt0 = -INFINITY, mt1 = -INFINITY;
        #pragma unroll
        for (int ni = 0; ni < 8; ++ni) {
            mt0 = fmaxf(mt0, fmaxf(sacc[ni][0], sacc[ni][1]));
            mt1 = fmaxf(mt1, fmaxf(sacc[ni][2], sacc[ni][3]));
        }
        mt0 = fmaxf(mt0, __shfl_xor_sync(0xffffffffu, mt0, 1));
        mt0 = fmaxf(mt0, __shfl_xor_sync(0xffffffffu, mt0, 2));
        mt1 = fmaxf(mt1, __shfl_xor_sync(0xffffffffu, mt1, 1));
        mt1 = fmaxf(mt1, __shfl_xor_sync(0xffffffffu, mt1, 2));
        const float mn0 = fmaxf(m0, mt0), mn1 = fmaxf(m1, mt1);
        const float sc0 = __expf(m0 - mn0), sc1 = __expf(m1 - mn1);
        m0 = mn0; m1 = mn1;
        float ls0 = 0.f, ls1 = 0.f;
        #pragma unroll
        for (int ni = 0; ni < 8; ++ni) {
            sacc[ni][0] = __expf(sacc[ni][0] - mn0);
            sacc[ni][1] = __expf(sacc[ni][1] - mn0);
            sacc[ni][2] = __expf(sacc[ni][2] - mn1);
            sacc[ni][3] = __expf(sacc[ni][3] - mn1);
            ls0 += sacc[ni][0] + sacc[ni][1];
            ls1 += sacc[ni][2] + sacc[ni][3];
        }
        ls0 += __shfl_xor_sync(0xffffffffu, ls0, 1);
        ls0 += __shfl_xor_sync(0xffffffffu, ls0, 2);
        ls1 += __shfl_xor_sync(0xffffffffu, ls1, 1);
        ls1 += __shfl_xor_sync(0xffffffffu, ls1, 2);
        l0 = l0 * sc0 + ls0;
        l1 = l1 * sc1 + ls1;
        #pragma unroll
        for (int ni = 0; ni < 8; ++ni) {
            oacc[ni][0] *= sc0; oacc[ni][1] *= sc0;
            oacc[ni][2] *= sc1; oacc[ni][3] *= sc1;
        }

        // ---- pack P into A-frags (hi/lo): a-frag s covers keys 16s..16s+15 ----
        u32 aPh[4][4], aPl[4][4];
        #pragma unroll
        for (int s = 0; s < 4; ++s) {
            #pragma unroll
            for (int half = 0; half < 2; ++half) {       // tiles 2s, 2s+1
                const float p0 = sacc[2 * s + half][0], p1 = sacc[2 * s + half][1];
                const float p2 = sacc[2 * s + half][2], p3 = sacc[2 * s + half][3];
                const u16 h0 = bf_hi(p0), h1 = bf_hi(p1), h2 = bf_hi(p2), h3 = bf_hi(p3);
                aPh[s][half * 2 + 0] = (u32)h0 | ((u32)h1 << 16);
                aPh[s][half * 2 + 1] = (u32)h2 | ((u32)h3 << 16);
                const u16 q0b = bf_lo(p0, h0), q1b = bf_lo(p1, h1);
                const u16 q2b = bf_lo(p2, h2), q3b = bf_lo(p3, h3);
                aPl[s][half * 2 + 0] = (u32)q0b | ((u32)q1b << 16);
                aPl[s][half * 2 + 1] = (u32)q2b | ((u32)q3b << 16);
            }
        }

        // ---- O += P V (bf16x3), V via ldmatrix.trans ----
        #pragma unroll
        for (int s = 0; s < 4; ++s) {
            u32 bVh[8][2], bVl[8][2];
            #pragma unroll
            for (int nd = 0; nd < 4; ++nd) {
                const uint32_t off = swz((uint32_t)((s * 16 + lr) * 128 + nd * 32 + ck * 16));
                u32 r[4];
                ldsm4t(r, st + 16384 + off);
                bVh[2 * nd][0] = r[0]; bVh[2 * nd][1] = r[1];
                bVh[2 * nd + 1][0] = r[2]; bVh[2 * nd + 1][1] = r[3];
                ldsm4t(r, st + 24576 + off);
                bVl[2 * nd][0] = r[0]; bVl[2 * nd][1] = r[1];
                bVl[2 * nd + 1][0] = r[2]; bVl[2 * nd + 1][1] = r[3];
            }
            #pragma unroll
            for (int ni = 0; ni < 8; ++ni) {
                mma_bf16(oacc[ni], aPh[s], bVh[ni]);
                mma_bf16(oacc[ni], aPh[s], bVl[ni]);
                mma_bf16(oacc[ni], aPl[s], bVh[ni]);
            }
        }
        __syncthreads();
    }

    // ---- writeout: o / l -> bf16 hi/lo y ----
    const float rl0 = 1.f / l0, rl1 = 1.f / l1;
    const int r0 = q0 + wid * 16 + gid, r1 = r0 + 8;
    #pragma unroll
    for (int ni = 0; ni < 8; ++ni) {
        const int col = h * HDIM + ni * 8 + qp * 2;
        {
            const float v0 = oacc[ni][0] * rl0, v1 = oacc[ni][1] * rl0;
            const u16 h0 = bf_hi(v0), h1 = bf_hi(v1);
            const u16 l0b = bf_lo(v0, h0), l1b = bf_lo(v1, h1);
            const size_t o = (tokbase + r0) * CDIM + col;
            *(u32*)(yh + o) = (u32)h0 | ((u32)h1 << 16);
            *(u32*)(yl + o) = (u32)l0b | ((u32)l1b << 16);
        }
        {
            const float v0 = oacc[ni][2] * rl1, v1 = oacc[ni][3] * rl1;
            const u16 h0 = bf_hi(v0), h1 = bf_hi(v1);
            const u16 l0b = bf_lo(v0, h0), l1b = bf_lo(v1, h1);
            const size_t o = (tokbase + r1) * CDIM + col;
            *(u32*)(yh + o) = (u32)h0 | ((u32)h1 << 16);
            *(u32*)(yl + o) = (u32)l0b | ((u32)l1b << 16);
        }
    }
}

// ---------------- residual + LayerNorm ----------------
__device__ __forceinline__ float block_sum256(float v, float* red) {
    const int lane = threadIdx.x & 31;
    const int w = threadIdx.x >> 5;
    #pragma unroll
    for (int off = 16; off; off >>= 1) v += __shfl_xor_sync(0xffffffffu, v, off);
    if (lane == 0) red[w] = v;
    __syncthreads();
    float t = (threadIdx.x < 8) ? red[threadIdx.x] : 0.f;
    if (w == 0) {
        t += __shfl_xor_sync(0xffffffffu, t, 4);
        t += __shfl_xor_sync(0xffffffffu, t, 2);
        t += __shfl_xor_sync(0xffffffffu, t, 1);
        if (lane == 0) red[0] = t;
    }
    __syncthreads();
    const float r = red[0];
    __syncthreads();
    return r;
}

template<bool PAIR>
__global__ __launch_bounds__(256) void add_ln_kernel(
    const float* __restrict__ xres, const float* __restrict__ v,
    const float* __restrict__ g, const float* __restrict__ be,
    float* __restrict__ out, u16* __restrict__ oh, u16* __restrict__ ol)
{
    __shared__ float red[8];
    const size_t row = blockIdx.x;
    const int c0 = threadIdx.x * 4;
    const float* vr = v + row * CDIM;

    float vals[4];
    *(float4*)vals = *(const float4*)(vr + c0);
    float s = vals[0] + vals[1] + vals[2] + vals[3];
    const float mean = block_sum256(s, red) * (1.f / CDIM);

    float d2 = 0.f;
    #pragma unroll
    for (int i = 0; i < 4; ++i) {
        const float d = vals[i] - mean;
        d2 = fmaf(d, d, d2);
    }
    const float var = block_sum256(d2, red) * (1.f / CDIM);
    const float rstd = rsqrtf(var + 1e-5f);

    float4 xr = *(const float4*)(xres + row * CDIM + c0);
    float4 gg = *(const float4*)(g + c0);
    float4 bb = *(const float4*)(be + c0);
    float4 res;
    res.x = xr.x + (vals[0] - mean) * rstd * gg.x + bb.x;
    res.y = xr.y + (vals[1] - mean) * rstd * gg.y + bb.y;
    res.z = xr.z + (vals[2] - mean) * rstd * gg.z + bb.z;
    res.w = xr.w + (vals[3] - mean) * rstd * gg.w + bb.w;
    *(float4*)(out + row * CDIM + c0) = res;
    if (PAIR) {
        u16 h0 = bf_hi(res.x), h1 = bf_hi(res.y), h2 = bf_hi(res.z), h3 = bf_hi(res.w);
        u16 l0 = bf_lo(res.x, h0), l1 = bf_lo(res.y, h1), l2 = bf_lo(res.z, h2), l3 = bf_lo(res.w, h3);
        *(uint2*)(oh + row * CDIM + c0) = make_uint2((u32)h0 | ((u32)h1 << 16), (u32)h2 | ((u32)h3 << 16));
        *(uint2*)(ol + row * CDIM + c0) = make_uint2((u32)l0 | ((u32)l1 << 16), (u32)l2 | ((u32)l3 << 16));
    }
}

// ---------------- launch ----------------
extern "C" void kernel_launch(void* const* d_in, const int* in_sizes, int n_in,
                              void* d_out, int out_size)
{
    const float* x      = (const float*)d_in[0];
    const float* w_attn = (const float*)d_in[1];
    const float* b_attn = (const float*)d_in[2];
    const float* wa1    = (const float*)d_in[3];
    const float* ba1    = (const float*)d_in[4];
    const float* wa2    = (const float*)d_in[5];
    const float* ba2    = (const float*)d_in[6];
    const float* g1     = (const float*)d_in[7];
    const float* be1    = (const float*)d_in[8];
    const float* wf1    = (const float*)d_in[9];
    const float* bf1    = (const float*)d_in[10];
    const float* wf2    = (const float*)d_in[11];
    const float* bf2    = (const float*)d_in[12];
    const float* g2     = (const float*)d_in[13];
    const float* be2    = (const float*)d_in[14];
    float* out = (float*)d_out;

    float *tbuf, *x1;
    u16 *xh, *xl, *qkvh, *qkvl, *yh, *yl, *x1h, *x1l, *hh, *hl;
    u16 *wah, *wal, *w1h, *w1l, *w2h, *w2l, *w3h, *w3l, *w4h, *w4l;
    cudaGetSymbolAddress((void**)&tbuf, g_t);
    cudaGetSymbolAddress((void**)&x1, g_x1);
    cudaGetSymbolAddress((void**)&xh, g_xh);     cudaGetSymbolAddress((void**)&xl, g_xl);
    cudaGetSymbolAddress((void**)&qkvh, g_qkvh); cudaGetSymbolAddress((void**)&qkvl, g_qkvl);
    cudaGetSymbolAddress((void**)&yh, g_yh);     cudaGetSymbolAddress((void**)&yl, g_yl);
    cudaGetSymbolAddress((void**)&x1h, g_x1h);   cudaGetSymbolAddress((void**)&x1l, g_x1l);
    cudaGetSymbolAddress((void**)&hh, g_hh);     cudaGetSymbolAddress((void**)&hl, g_hl);
    cudaGetSymbolAddress((void**)&wah, g_wah);   cudaGetSymbolAddress((void**)&wal, g_wal);
    cudaGetSymbolAddress((void**)&w1h, g_w1h);   cudaGetSymbolAddress((void**)&w1l, g_w1l);
    cudaGetSymbolAddress((void**)&w2h, g_w2h);   cudaGetSymbolAddress((void**)&w2l, g_w2l);
    cudaGetSymbolAddress((void**)&w3h, g_w3h);   cudaGetSymbolAddress((void**)&w3l, g_w3l);
    cudaGetSymbolAddress((void**)&w4h, g_w4h);   cudaGetSymbolAddress((void**)&w4l, g_w4l);

    cudaFuncSetAttribute(mma_gemm<0>, cudaFuncAttributeMaxDynamicSharedMemorySize, MG_SMEM);
    cudaFuncSetAttribute(mma_gemm<1>, cudaFuncAttributeMaxDynamicSharedMemorySize, MG_SMEM);
    cudaFuncSetAttribute(mma_gemm<2>, cudaFuncAttributeMaxDynamicSharedMemorySize, MG_SMEM);
    cudaFuncSetAttribute(attn_mma, cudaFuncAttributeMaxDynamicSharedMemorySize, ATT_SMEM);

    const dim3 tb(32, 8);
    tdecomp_k<<<dim3(3 * CDIM / 32, CDIM / 32), tb>>>(w_attn, wah, wal, CDIM, 3 * CDIM);
    tdecomp_k<<<dim3(HID / 32, CDIM / 32), tb>>>(wa1, w1h, w1l, CDIM, HID);
    tdecomp_k<<<dim3(CDIM / 32, HID / 32), tb>>>(wa2, w2h, w2l, HID, CDIM);
    tdecomp_k<<<dim3(HID / 32, CDIM / 32), tb>>>(wf1, w3h, w3l, CDIM, HID);
    tdecomp_k<<<dim3(CDIM / 32, HID / 32), tb>>>(wf2, w4h, w4l, HID, CDIM);
    decomp_k<<<(ROWS * CDIM / 4 + 255) / 256, 256>>>(x, xh, xl, ROWS * CDIM / 4);

    // 1) qkv = x @ w_attn + b_attn -> bf16 hi/lo directly
    mma_gemm<2><<<dim3(3 * CDIM / 128, ROWS / 128), 256, MG_SMEM>>>(
        xh, xl, wah, wal, b_attn, nullptr, qkvh, qkvl, 3 * CDIM, CDIM);

    // 2) causal MHA (tensor cores) -> y hi/lo
    attn_mma<<<dim3(SEQ / 64, NHEAD, BATCH), 128, ATT_SMEM>>>(qkvh, qkvl, yh, yl);

    // 3) h = gelu(y @ wa1 + ba1) -> bf16 hi/lo
    mma_gemm<1><<<dim3(HID / 128, ROWS / 128), 256, MG_SMEM>>>(
        yh, yl, w1h, w1l, ba1, nullptr, hh, hl, HID, CDIM);

    // 4) t = h @ wa2 + ba2 (fp32)
    mma_gemm<0><<<dim3(CDIM / 128, ROWS / 128), 256, MG_SMEM>>>(
        hh, hl, w2h, w2l, ba2, tbuf, nullptr, nullptr, CDIM, HID);

    // 5) x1 = x + LN(t)
    add_ln_kernel<true><<<ROWS, 256>>>(x, tbuf, g1, be1, x1, x1h, x1l);

    // 6) h = gelu(x1 @ wf1 + bf1) -> bf16 hi/lo
    mma_gemm<1><<<dim3(HID / 128, ROWS / 128), 256, MG_SMEM>>>(
        x1h, x1l, w3h, w3l, bf1, nullptr, hh, hl, HID, CDIM);

    // 7) t = h @ wf2 + bf2 (fp32)
    mma_gemm<0><<<dim3(CDIM / 128, ROWS / 128), 256, MG_SMEM>>>(
        hh, hl, w4h, w4l, bf2, tbuf, nullptr, nullptr, CDIM, HID);

    // 8) out = x1 + LN(t)
    add_ln_kernel<false><<<ROWS, 256>>>(x1, tbuf, g2, be2, out, nullptr, nullptr);
}